// round 2
// baseline (speedup 1.0000x reference)
#include <cuda_runtime.h>
#include <cstdint>

// MaxUnpooling2D: B=16, H=128, W=128, C=64, S=2 -> out (16, 256, 256, 64)
// Each (h,w,c) scatters into its OWN 2x2 window at channel c (unique owner per
// output cell) -> one-pass window write, no atomics, no memset.
//
// R2: streaming cache hints (__ldcs/__stcs) + 4 elements/thread with
// front-batched loads (MLP_p1=8) to push DRAM efficiency toward the ceiling.

static constexpr int B = 16;
static constexpr int H = 128;
static constexpr int W = 128;
static constexpr int C = 64;
static constexpr int Wo = 256;   // W*2
static constexpr int IPT = 4;    // float4-elements per thread

__global__ __launch_bounds__(256) void unpool_kernel(
    const float4* __restrict__ upd4,
    const int4* __restrict__ msk4,
    float* __restrict__ out)
{
    int base_idx = blockIdx.x * (256 * IPT) + threadIdx.x;

    float4 u[IPT];
    int4   m[IPT];

    // Front-batched loads: 8 independent 16B loads in flight per thread.
#pragma unroll
    for (int j = 0; j < IPT; j++) {
        int idx = base_idx + j * 256;
        u[j] = __ldcs(&upd4[idx]);
        m[j] = __ldcs(&msk4[idx]);
    }

#pragma unroll
    for (int j = 0; j < IPT; j++) {
        int idx = base_idx + j * 256;
        // idx layout: [ b*H + h ][ w ][ c4 ], c4 in [0,16)
        int c4 = idx & 15;
        int w  = (idx >> 4) & (W - 1);
        int hb = idx >> 11;        // b*H + h

        float4 v0 = {0.f, 0.f, 0.f, 0.f};
        float4 v1 = v0, v2 = v0, v3 = v0;

        // t = mask >> 6 (= y*Wo + x); dx = t & 1; dy = (t >> 8) & 1; q = dy*2+dx
#define PLACE(comp)                                                   \
        {                                                             \
            int t = m[j].comp >> 6;                                   \
            int q = ((t >> 7) & 2) | (t & 1);                         \
            v0.comp = (q == 0) ? u[j].comp : 0.f;                     \
            v1.comp = (q == 1) ? u[j].comp : 0.f;                     \
            v2.comp = (q == 2) ? u[j].comp : 0.f;                     \
            v3.comp = (q == 3) ? u[j].comp : 0.f;                     \
        }
        PLACE(x) PLACE(y) PLACE(z) PLACE(w)
#undef PLACE

        // output base: (2*hb*Wo + 2*w) * C + c4*4
        int obase = ((hb * Wo + w) << 1) * C + (c4 << 2);

        __stcs(reinterpret_cast<float4*>(out + obase),              v0); // (2h,  2w  )
        __stcs(reinterpret_cast<float4*>(out + obase + C),          v1); // (2h,  2w+1)
        __stcs(reinterpret_cast<float4*>(out + obase + Wo * C),     v2); // (2h+1,2w  )
        __stcs(reinterpret_cast<float4*>(out + obase + Wo * C + C), v3); // (2h+1,2w+1)
    }
}

extern "C" void kernel_launch(void* const* d_in, const int* in_sizes, int n_in,
                              void* d_out, int out_size)
{
    const float4* upd4 = (const float4*)d_in[0];
    const int4*   msk4 = (const int4*)d_in[1];
    float*        out  = (float*)d_out;

    int n4 = (B * H * W * C) / 4;            // 4,194,304 float4 elements
    int threads = 256;
    int blocks = n4 / (threads * IPT);       // 4096
    unpool_kernel<<<blocks, threads>>>(upd4, msk4, out);
}

// round 3
// speedup vs baseline: 1.0015x; 1.0015x over previous
#include <cuda_runtime.h>
#include <cstdint>

// MaxUnpooling2D: B=16, H=128, W=128, C=64, S=2 -> out (16, 256, 256, 64)
// Each (h,w,c) scatters into its OWN 2x2 window at channel c (unique owner per
// output cell) -> one-pass window write, no atomics, no memset.
//
// R3: R1 structure (1 float4/thread, 22 regs, occ ~76%) + streaming cache
// hints only (__ldcs/__stcs). R2 showed IPT batching kills occupancy.

static constexpr int B = 16;
static constexpr int H = 128;
static constexpr int W = 128;
static constexpr int C = 64;
static constexpr int Wo = 256;   // W*2

__global__ __launch_bounds__(256) void unpool_kernel(
    const float4* __restrict__ upd4,
    const int4* __restrict__ msk4,
    float* __restrict__ out)
{
    int tid = blockIdx.x * blockDim.x + threadIdx.x;   // one thread = 4 channels
    // tid layout: [ b*H + h ][ w ][ c4 ], c4 in [0,16)
    int c4 = tid & 15;
    int w  = (tid >> 4) & (W - 1);
    int hb = tid >> 11;            // b*H + h

    float4 u = __ldcs(&upd4[tid]);
    int4   m = __ldcs(&msk4[tid]);

    float4 v0 = {0.f, 0.f, 0.f, 0.f};
    float4 v1 = v0, v2 = v0, v3 = v0;

    // t = mask >> 6 (= y*Wo + x); dx = t & 1; dy = (t >> 8) & 1; q = dy*2+dx
#define PLACE(comp)                                                   \
    {                                                                 \
        int t = m.comp >> 6;                                          \
        int q = ((t >> 7) & 2) | (t & 1);                             \
        v0.comp = (q == 0) ? u.comp : 0.f;                            \
        v1.comp = (q == 1) ? u.comp : 0.f;                            \
        v2.comp = (q == 2) ? u.comp : 0.f;                            \
        v3.comp = (q == 3) ? u.comp : 0.f;                            \
    }
    PLACE(x) PLACE(y) PLACE(z) PLACE(w)
#undef PLACE

    // output base: (2*hb*Wo + 2*w) * C + c4*4
    int base = ((hb * Wo + w) << 1) * C + (c4 << 2);

    __stcs(reinterpret_cast<float4*>(out + base),              v0); // (2h,  2w  )
    __stcs(reinterpret_cast<float4*>(out + base + C),          v1); // (2h,  2w+1)
    __stcs(reinterpret_cast<float4*>(out + base + Wo * C),     v2); // (2h+1,2w  )
    __stcs(reinterpret_cast<float4*>(out + base + Wo * C + C), v3); // (2h+1,2w+1)
}

extern "C" void kernel_launch(void* const* d_in, const int* in_sizes, int n_in,
                              void* d_out, int out_size)
{
    const float4* upd4 = (const float4*)d_in[0];
    const int4*   msk4 = (const int4*)d_in[1];
    float*        out  = (float*)d_out;

    int n4 = (B * H * W * C) / 4;            // 4,194,304 threads
    int threads = 256;
    int blocks = n4 / threads;               // 16384
    unpool_kernel<<<blocks, threads>>>(upd4, msk4, out);
}